// round 2
// baseline (speedup 1.0000x reference)
#include <cuda_runtime.h>

#define B_ 2048
#define T_ 128
#define D_ 128
#define H_ 64
#define G_ 256   // 4*H

// 256 MB scratch for XZ1, layout [t][b][g] (t-major so the scan reads coalesced per step)
__device__ float g_xz1[(size_t)T_ * B_ * G_];

__device__ __forceinline__ float sigf(float x) {
    return __fdividef(1.f, 1.f + __expf(-x));
}
__device__ __forceinline__ float tanhf_(float x) {
    return 2.f * __fdividef(1.f, 1.f + __expf(-2.f * x)) - 1.f;
}

// ---------------------------------------------------------------------------
// Kernel 1: XZ1[t][b][g] = sum_d x[b][t][d] * W1[d][g] + b1[g]
// x flattened as (m = b*T + t) rows of 128. Block = 32 rows x 256 cols.
// ---------------------------------------------------------------------------
#define GR 32
__global__ void __launch_bounds__(256) xz1_gemm_kernel(
    const float* __restrict__ x, const float* __restrict__ W1,
    const float* __restrict__ b1)
{
    __shared__ float xs[GR * (D_ + 4)];
    const int tid = threadIdx.x;
    const int m0 = blockIdx.x * GR;

    // stage 32 rows of x (each row = 128 contiguous floats)
    const float4* xsrc = (const float4*)(x + (size_t)m0 * D_);
    #pragma unroll
    for (int i = 0; i < (GR * D_ / 4) / 256; i++) {
        int idx = i * 256 + tid;
        int r = idx >> 5;          // / (D_/4)
        int d4 = idx & 31;
        *(float4*)(xs + r * (D_ + 4) + d4 * 4) = xsrc[idx];
    }
    __syncthreads();

    const int g = tid;
    float bias = b1[g];
    float acc[GR];
    #pragma unroll
    for (int r = 0; r < GR; r++) acc[r] = bias;

    const float* Wp = W1 + g;
    #pragma unroll 2
    for (int k = 0; k < D_; k += 4) {
        float w0 = Wp[(k + 0) * G_];
        float w1 = Wp[(k + 1) * G_];
        float w2 = Wp[(k + 2) * G_];
        float w3 = Wp[(k + 3) * G_];
        #pragma unroll
        for (int r = 0; r < GR; r++) {
            float4 xv = *(const float4*)(xs + r * (D_ + 4) + k);
            acc[r] = fmaf(xv.w, w3, fmaf(xv.z, w2, fmaf(xv.y, w1, fmaf(xv.x, w0, acc[r]))));
        }
    }

    #pragma unroll
    for (int r = 0; r < GR; r++) {
        int m = m0 + r;
        int bb = m >> 7;    // / T_
        int tt = m & 127;   // % T_
        g_xz1[(size_t)tt * (B_ * G_) + (size_t)bb * G_ + g] = acc[r];
    }
}

// ---------------------------------------------------------------------------
// Kernel 2: fused persistent 2-layer LSTM scan.
// 128 CTAs x 256 threads; CTA owns BT=16 batch rows for all T steps.
// smem: U1 | W2 | U2 | b2 | h1[k][b] | h2[k][b] | z[16][257]
// ---------------------------------------------------------------------------
#define BT 16
#define SMEM_FLOATS 55568   // 16384*3 + 256 + 1024 + 1024 + 16*257

__global__ void __launch_bounds__(256, 1) lstm_scan_kernel(
    const float* __restrict__ U1g, const float* __restrict__ W2g,
    const float* __restrict__ U2g, const float* __restrict__ b2g,
    float* __restrict__ out)
{
    extern __shared__ float sm[];
    float* U1s = sm;                 // 16384
    float* W2s = sm + 16384;         // 16384
    float* U2s = sm + 32768;         // 16384
    float* b2s = sm + 49152;         // 256
    float* h1s = sm + 49408;         // [64][16]
    float* h2s = sm + 50432;         // [64][16]
    float* zs  = sm + 51456;         // [16][257] (pad 257 -> conflict-free reads)

    const int tid = threadIdx.x;
    const int g = tid;                       // GEMM-phase column 0..255
    const int b0g = blockIdx.x * BT;

    for (int i = tid; i < 16384; i += 256) {
        U1s[i] = U1g[i];
        W2s[i] = W2g[i];
        U2s[i] = U2g[i];
    }
    b2s[tid] = b2g[tid];
    for (int i = tid; i < 2048; i += 256) h1s[i] = 0.f;  // zeroes h1s + h2s

    // elementwise mapping: thread -> (h = tid/4, batch rows eb0..eb0+3)
    const int eh = tid >> 2;
    const int eb0 = (tid & 3) << 2;
    float c1[4] = {0.f, 0.f, 0.f, 0.f};
    float c2[4] = {0.f, 0.f, 0.f, 0.f};
    __syncthreads();

    const float* xzbase = g_xz1 + (size_t)b0g * G_ + g;

    for (int t = 0; t < T_; t++) {
        // ---- phase A: z1 = XZ1[t] + h1_prev @ U1 ----
        // Issue XZ1 loads first; ~4K fma-cycles of GEMM below hides DRAM latency.
        float xz[BT];
        {
            const float* xzp = xzbase + (size_t)t * (B_ * G_);
            #pragma unroll
            for (int r = 0; r < BT; r++) xz[r] = xzp[(size_t)r * G_];
        }
        float acc[BT];
        #pragma unroll
        for (int r = 0; r < BT; r++) acc[r] = 0.f;

        #pragma unroll 4
        for (int k = 0; k < H_; k++) {
            float u = U1s[(k << 8) + g];
            float hv[16];
            *(float4*)(hv)      = *(const float4*)(h1s + (k << 4));
            *(float4*)(hv + 4)  = *(const float4*)(h1s + (k << 4) + 4);
            *(float4*)(hv + 8)  = *(const float4*)(h1s + (k << 4) + 8);
            *(float4*)(hv + 12) = *(const float4*)(h1s + (k << 4) + 12);
            #pragma unroll
            for (int r = 0; r < BT; r++) acc[r] = fmaf(hv[r], u, acc[r]);
        }
        #pragma unroll
        for (int r = 0; r < BT; r++) zs[r * 257 + g] = acc[r] + xz[r];
        __syncthreads();

        // ---- phase B: layer-1 gates (act = tanh) ----
        {
            float hn[4];
            #pragma unroll
            for (int j = 0; j < 4; j++) {
                const float* zr = zs + (eb0 + j) * 257 + eh;
                float ig = sigf(zr[0]);
                float fg = sigf(zr[64]);
                float gg = tanhf_(zr[128]);
                float og = sigf(zr[192]);
                c1[j] = fmaf(fg, c1[j], ig * gg);
                hn[j] = og * tanhf_(c1[j]);
            }
            *(float4*)(h1s + (eh << 4) + eb0) = make_float4(hn[0], hn[1], hn[2], hn[3]);
        }
        __syncthreads();

        // ---- phase C: z2 = h1_new @ W2 + h2_prev @ U2 + b2 ----
        float acc2[BT];
        {
            float bias = b2s[g];
            #pragma unroll
            for (int r = 0; r < BT; r++) acc2[r] = bias;
        }
        #pragma unroll 2
        for (int k = 0; k < H_; k++) {
            float w = W2s[(k << 8) + g];
            float u = U2s[(k << 8) + g];
            float av[16], pv[16];
            *(float4*)(av)      = *(const float4*)(h1s + (k << 4));
            *(float4*)(av + 4)  = *(const float4*)(h1s + (k << 4) + 4);
            *(float4*)(av + 8)  = *(const float4*)(h1s + (k << 4) + 8);
            *(float4*)(av + 12) = *(const float4*)(h1s + (k << 4) + 12);
            *(float4*)(pv)      = *(const float4*)(h2s + (k << 4));
            *(float4*)(pv + 4)  = *(const float4*)(h2s + (k << 4) + 4);
            *(float4*)(pv + 8)  = *(const float4*)(h2s + (k << 4) + 8);
            *(float4*)(pv + 12) = *(const float4*)(h2s + (k << 4) + 12);
            #pragma unroll
            for (int r = 0; r < BT; r++) acc2[r] = fmaf(av[r], w, fmaf(pv[r], u, acc2[r]));
        }
        #pragma unroll
        for (int r = 0; r < BT; r++) zs[r * 257 + g] = acc2[r];
        __syncthreads();

        // ---- phase D: layer-2 gates (act = sigmoid) + output store ----
        {
            float hn[4];
            #pragma unroll
            for (int j = 0; j < 4; j++) {
                const float* zr = zs + (eb0 + j) * 257 + eh;
                float ig = sigf(zr[0]);
                float fg = sigf(zr[64]);
                float gg = sigf(zr[128]);
                float og = sigf(zr[192]);
                c2[j] = fmaf(fg, c2[j], ig * gg);
                hn[j] = og * sigf(c2[j]);
                out[(size_t)(b0g + eb0 + j) * (T_ * H_) + t * H_ + eh] = hn[j];
            }
            *(float4*)(h2s + (eh << 4) + eb0) = make_float4(hn[0], hn[1], hn[2], hn[3]);
        }
        __syncthreads();
    }
}

// ---------------------------------------------------------------------------
extern "C" void kernel_launch(void* const* d_in, const int* in_sizes, int n_in,
                              void* d_out, int out_size)
{
    const float* x  = (const float*)d_in[0];
    const float* W1 = (const float*)d_in[1];
    const float* U1 = (const float*)d_in[2];
    const float* b1 = (const float*)d_in[3];
    const float* W2 = (const float*)d_in[4];
    const float* U2 = (const float*)d_in[5];
    const float* b2 = (const float*)d_in[6];
    float* out = (float*)d_out;

    xz1_gemm_kernel<<<(B_ * T_) / GR, 256>>>(x, W1, b1);

    cudaFuncSetAttribute(lstm_scan_kernel,
                         cudaFuncAttributeMaxDynamicSharedMemorySize,
                         SMEM_FLOATS * (int)sizeof(float));
    lstm_scan_kernel<<<B_ / BT, 256, SMEM_FLOATS * sizeof(float)>>>(U1, W2, U2, b2, out);
}

// round 3
// speedup vs baseline: 1.3131x; 1.3131x over previous
#include <cuda_runtime.h>

typedef unsigned long long ull;

#define B_ 2048
#define T_ 128
#define D_ 128
#define H_ 64
#define G_ 256   // 4*H

// 128 MB scratch for XZ1, layout [t][b][g]
__device__ float g_xz1[(size_t)T_ * B_ * G_];

// ---------------- f32x2 helpers (Blackwell packed fp32) ----------------
__device__ __forceinline__ ull splat2(float v) {
    ull r; asm("mov.b64 %0,{%1,%1};" : "=l"(r) : "f"(v)); return r;
}
__device__ __forceinline__ ull pack2(float lo, float hi) {
    ull r; asm("mov.b64 %0,{%1,%2};" : "=l"(r) : "f"(lo), "f"(hi)); return r;
}
__device__ __forceinline__ ull ffma2(ull a, ull b, ull c) {
    ull d; asm("fma.rn.f32x2 %0,%1,%2,%3;" : "=l"(d) : "l"(a), "l"(b), "l"(c)); return d;
}
__device__ __forceinline__ ull add2(ull a, ull b) {
    ull d; asm("add.rn.f32x2 %0,%1,%2;" : "=l"(d) : "l"(a), "l"(b)); return d;
}
__device__ __forceinline__ float2 unpack2(ull v) {
    float2 f; asm("mov.b64 {%0,%1},%2;" : "=f"(f.x), "=f"(f.y) : "l"(v)); return f;
}

__device__ __forceinline__ float sigf(float x) {
    return __fdividef(1.f, 1.f + __expf(-x));
}
__device__ __forceinline__ float tanhf_(float x) {
    return 2.f * __fdividef(1.f, 1.f + __expf(-2.f * x)) - 1.f;
}

// ---------------------------------------------------------------------------
// Kernel 1: XZ1[t][b][g] = sum_d x[b][t][d] * W1[d][g] + b1[g]
// Block = 32 rows x 256 cols. Rows packed as f32x2 pairs (r, r+16) in smem.
// ---------------------------------------------------------------------------
#define GR 32
__global__ void __launch_bounds__(256) xz1_gemm_kernel(
    const float* __restrict__ x, const float* __restrict__ W1,
    const float* __restrict__ b1)
{
    __shared__ ull xp[D_ * 16];   // [d][pair], pair p = rows (p, p+16)
    const int tid = threadIdx.x;
    const int m0 = blockIdx.x * GR;

    // stage + row-pair pack
    const float4* xv = (const float4*)x;
    #pragma unroll
    for (int i = 0; i < 2; i++) {
        int u = tid + i * 256;
        int p = u >> 5, c4 = u & 31;
        float4 a = xv[(size_t)(m0 + p) * 32 + c4];
        float4 b = xv[(size_t)(m0 + p + 16) * 32 + c4];
        xp[(4 * c4 + 0) * 16 + p] = pack2(a.x, b.x);
        xp[(4 * c4 + 1) * 16 + p] = pack2(a.y, b.y);
        xp[(4 * c4 + 2) * 16 + p] = pack2(a.z, b.z);
        xp[(4 * c4 + 3) * 16 + p] = pack2(a.w, b.w);
    }
    __syncthreads();

    const int g = tid;
    ull bias = splat2(b1[g]);
    ull acc[16];
    #pragma unroll
    for (int p = 0; p < 16; p++) acc[p] = bias;

    const float* Wp = W1 + g;
    #pragma unroll 2
    for (int k = 0; k < D_; k += 4) {
        // prefetch 4 weights (coalesced LDG, L1/L2 resident)
        float w0 = Wp[(k + 0) * G_];
        float w1 = Wp[(k + 1) * G_];
        float w2 = Wp[(k + 2) * G_];
        float w3 = Wp[(k + 3) * G_];
        ull ws0 = splat2(w0), ws1 = splat2(w1), ws2 = splat2(w2), ws3 = splat2(w3);
        #pragma unroll
        for (int kk = 0; kk < 4; kk++) {
            ull ws = (kk == 0) ? ws0 : (kk == 1) ? ws1 : (kk == 2) ? ws2 : ws3;
            const ull* xr = xp + (k + kk) * 16;
            #pragma unroll
            for (int p = 0; p < 16; p += 2) {
                ulonglong2 q = *(const ulonglong2*)(xr + p);  // LDS.128 broadcast
                acc[p]     = ffma2(q.x, ws, acc[p]);
                acc[p + 1] = ffma2(q.y, ws, acc[p + 1]);
            }
        }
    }

    #pragma unroll
    for (int p = 0; p < 16; p++) {
        float2 v = unpack2(acc[p]);
        int m = m0 + p;
        g_xz1[(size_t)(m & 127) * (B_ * G_) + (size_t)(m >> 7) * G_ + g] = v.x;
        m = m0 + p + 16;
        g_xz1[(size_t)(m & 127) * (B_ * G_) + (size_t)(m >> 7) * G_ + g] = v.y;
    }
}

// ---------------------------------------------------------------------------
// Kernel 2: fused persistent 2-layer LSTM scan, f32x2 GEMM phases.
// 128 CTAs x 256 threads; CTA owns BT=16 batch rows for all T steps.
// GEMM mapping: thread -> 2 gate cols (f32x2 pair) x 8 batch rows.
// ---------------------------------------------------------------------------
#define BT 16
#define ZP 258   // zs row pad: even (8B-aligned ull) + conflict-free
#define SMEM_FLOATS (49152 + 256 + 1024 + 1024 + BT * ZP)

__global__ void __launch_bounds__(256, 1) lstm_scan_kernel(
    const float* __restrict__ U1g, const float* __restrict__ W2g,
    const float* __restrict__ U2g, const float* __restrict__ b2g,
    float* __restrict__ out)
{
    extern __shared__ float sm[];
    float* U1s = sm;                 // 16384  [k][256]
    float* W2s = sm + 16384;         // 16384
    float* U2s = sm + 32768;         // 16384
    float* b2s = sm + 49152;         // 256
    float* h1s = sm + 49408;         // 1024  [k][16]
    float* h2s = sm + 50432;         // 1024
    float* zs  = sm + 51456;         // [16][258]

    const int tid = threadIdx.x;
    const int b0g = blockIdx.x * BT;

    for (int i = tid; i < 16384; i += 256) {
        U1s[i] = U1g[i];
        W2s[i] = W2g[i];
        U2s[i] = U2g[i];
    }
    b2s[tid] = b2g[tid];
    for (int i = tid; i < 2048; i += 256) h1s[i] = 0.f;  // zeroes h1s + h2s

    // GEMM-phase mapping: 2 cols x 8 rows
    const int g0 = (tid & 127) << 1;     // gate col pair base (even)
    const int b0 = (tid >> 7) << 3;      // batch sub-block: 0 or 8
    // elementwise mapping: thread -> (h = tid/4, 4 batch rows)
    const int eh = tid >> 2;
    const int eb0 = (tid & 3) << 2;
    float c1[4] = {0.f, 0.f, 0.f, 0.f};
    float c2[4] = {0.f, 0.f, 0.f, 0.f};
    __syncthreads();

    const float* xzb = g_xz1 + (size_t)(b0g + b0) * G_ + g0;

    for (int t = 0; t < T_; t++) {
        // ---- phase A: z1 = XZ1[t] + h1_prev @ U1 ----
        // issue gmem loads first; entire k-loop hides their latency
        ull xzv[8];
        {
            const float* xzp = xzb + (size_t)t * (B_ * G_);
            #pragma unroll
            for (int j = 0; j < 8; j++)
                xzv[j] = *(const ull*)(xzp + (size_t)j * G_);
        }
        ull acc[8];
        #pragma unroll
        for (int j = 0; j < 8; j++) acc[j] = 0ull;

        #pragma unroll 8
        for (int k = 0; k < H_; k++) {
            ull u = *(const ull*)(U1s + (k << 8) + g0);            // LDS.64
            float4 ha = *(const float4*)(h1s + (k << 4) + b0);     // bcast
            float4 hb = *(const float4*)(h1s + (k << 4) + b0 + 4);
            acc[0] = ffma2(splat2(ha.x), u, acc[0]);
            acc[1] = ffma2(splat2(ha.y), u, acc[1]);
            acc[2] = ffma2(splat2(ha.z), u, acc[2]);
            acc[3] = ffma2(splat2(ha.w), u, acc[3]);
            acc[4] = ffma2(splat2(hb.x), u, acc[4]);
            acc[5] = ffma2(splat2(hb.y), u, acc[5]);
            acc[6] = ffma2(splat2(hb.z), u, acc[6]);
            acc[7] = ffma2(splat2(hb.w), u, acc[7]);
        }
        #pragma unroll
        for (int j = 0; j < 8; j++)
            *(ull*)(zs + (b0 + j) * ZP + g0) = add2(acc[j], xzv[j]);
        __syncthreads();

        // ---- phase B: layer-1 gates (act = tanh) ----
        {
            float hn[4];
            #pragma unroll
            for (int j = 0; j < 4; j++) {
                const float* zr = zs + (eb0 + j) * ZP + eh;
                float ig = sigf(zr[0]);
                float fg = sigf(zr[64]);
                float gg = tanhf_(zr[128]);
                float og = sigf(zr[192]);
                c1[j] = fmaf(fg, c1[j], ig * gg);
                hn[j] = og * tanhf_(c1[j]);
            }
            *(float4*)(h1s + (eh << 4) + eb0) = make_float4(hn[0], hn[1], hn[2], hn[3]);
        }
        __syncthreads();

        // ---- phase C: z2 = h1_new @ W2 + h2_prev @ U2 + b2 ----
        ull acc2[8];
        {
            ull bias = *(const ull*)(b2s + g0);
            #pragma unroll
            for (int j = 0; j < 8; j++) acc2[j] = bias;
        }
        #pragma unroll 4
        for (int k = 0; k < H_; k++) {
            ull uw = *(const ull*)(W2s + (k << 8) + g0);
            ull uu = *(const ull*)(U2s + (k << 8) + g0);
            float4 ha = *(const float4*)(h1s + (k << 4) + b0);
            float4 hb = *(const float4*)(h1s + (k << 4) + b0 + 4);
            float4 pa = *(const float4*)(h2s + (k << 4) + b0);
            float4 pb = *(const float4*)(h2s + (k << 4) + b0 + 4);
            acc2[0] = ffma2(splat2(ha.x), uw, ffma2(splat2(pa.x), uu, acc2[0]));
            acc2[1] = ffma2(splat2(ha.y), uw, ffma2(splat2(pa.y), uu, acc2[1]));
            acc2[2] = ffma2(splat2(ha.z), uw, ffma2(splat2(pa.z), uu, acc2[2]));
            acc2[3] = ffma2(splat2(ha.w), uw, ffma2(splat2(pa.w), uu, acc2[3]));
            acc2[4] = ffma2(splat2(hb.x), uw, ffma2(splat2(pb.x), uu, acc2[4]));
            acc2[5] = ffma2(splat2(hb.y), uw, ffma2(splat2(pb.y), uu, acc2[5]));
            acc2[6] = ffma2(splat2(hb.z), uw, ffma2(splat2(pb.z), uu, acc2[6]));
            acc2[7] = ffma2(splat2(hb.w), uw, ffma2(splat2(pb.w), uu, acc2[7]));
        }
        #pragma unroll
        for (int j = 0; j < 8; j++)
            *(ull*)(zs + (b0 + j) * ZP + g0) = acc2[j];
        __syncthreads();

        // ---- phase D: layer-2 gates (act = sigmoid) + output store ----
        {
            float hn[4];
            #pragma unroll
            for (int j = 0; j < 4; j++) {
                const float* zr = zs + (eb0 + j) * ZP + eh;
                float ig = sigf(zr[0]);
                float fg = sigf(zr[64]);
                float gg = sigf(zr[128]);
                float og = sigf(zr[192]);
                c2[j] = fmaf(fg, c2[j], ig * gg);
                hn[j] = og * sigf(c2[j]);
                out[(size_t)(b0g + eb0 + j) * (T_ * H_) + t * H_ + eh] = hn[j];
            }
            *(float4*)(h2s + (eh << 4) + eb0) = make_float4(hn[0], hn[1], hn[2], hn[3]);
        }
        __syncthreads();
    }
}

// ---------------------------------------------------------------------------
extern "C" void kernel_launch(void* const* d_in, const int* in_sizes, int n_in,
                              void* d_out, int out_size)
{
    const float* x  = (const float*)d_in[0];
    const float* W1 = (const float*)d_in[1];
    const float* U1 = (const float*)d_in[2];
    const float* b1 = (const float*)d_in[3];
    const float* W2 = (const float*)d_in[4];
    const float* U2 = (const float*)d_in[5];
    const float* b2 = (const float*)d_in[6];
    float* out = (float*)d_out;

    xz1_gemm_kernel<<<(B_ * T_) / GR, 256>>>(x, W1, b1);

    cudaFuncSetAttribute(lstm_scan_kernel,
                         cudaFuncAttributeMaxDynamicSharedMemorySize,
                         SMEM_FLOATS * (int)sizeof(float));
    lstm_scan_kernel<<<B_ / BT, 256, SMEM_FLOATS * sizeof(float)>>>(U1, W2, U2, b2, out);
}